// round 3
// baseline (speedup 1.0000x reference)
#include <cuda_runtime.h>
#include <math.h>

#define NB   133      // persistent grid size (<= 148 SMs, all co-resident)
#define NT   256
#define GSZ  100
#define OUTS 8450

// Scratch + barrier state (no cudaMalloc allowed)
__device__ float g_h0[128 * 512];
__device__ float g_h1[128 * 512];
__device__ float g_h2[128 * 512];
__device__ float g_wab[128 * OUTS];
__device__ unsigned g_bar;   // monotonic ticket counter (never reset; replay-safe)

// ---------------------------------------------------------------------------
// Packed fp32x2 FMA (Blackwell FFMA2) — 2 MAC per issue slot
// ---------------------------------------------------------------------------
__device__ __forceinline__ float2 ffma2(float2 a, float2 b, float2 c) {
    float2 d;
    asm("{\n\t"
        ".reg .b64 A,B,C,D;\n\t"
        "mov.b64 A,{%2,%3};\n\t"
        "mov.b64 B,{%4,%5};\n\t"
        "mov.b64 C,{%6,%7};\n\t"
        "fma.rn.f32x2 D,A,B,C;\n\t"
        "mov.b64 {%0,%1},D;\n\t"
        "}"
        : "=f"(d.x), "=f"(d.y)
        : "f"(a.x), "f"(a.y), "f"(b.x), "f"(b.y), "f"(c.x), "f"(c.y));
    return d;
}

// ---------------------------------------------------------------------------
// Grid-wide barrier: ticket + generation. Works across graph replays because
// the counter is monotonic (generation arithmetic, no reset).
// ---------------------------------------------------------------------------
__device__ __forceinline__ void grid_barrier() {
    __syncthreads();
    __threadfence();
    if (threadIdx.x == 0) {
        unsigned my = atomicAdd(&g_bar, 1u);
        unsigned target = my - (my % NB) + NB;
        while ((int)(*(volatile unsigned*)&g_bar - target) < 0)
            __nanosleep(32);
    }
    __syncthreads();
}

// ---------------------------------------------------------------------------
// Hidden layer: C[128,512] = leaky(A[128,512] @ W[512,512] + b)
// 128 active blocks = 16 m-slices(8 rows) x 8 n-slices(64 cols).
// Threads: ng = t&7 (8 cols each), mg = (t>>3)&3 (2 rows each), h = t>>5
// (8-way k-split of 64 per 64-k tile), smem tree-reduce over h.
// smem: As[512][8] @0, Ws[64][64] @4096, red[256][17] @8192
// ---------------------------------------------------------------------------
__device__ void h_layer(const float* __restrict__ Ain,
                        const float* __restrict__ W,
                        const float* __restrict__ bias,
                        float* __restrict__ Aout,
                        float* s)
{
    if (blockIdx.x >= 128) return;
    const int t = threadIdx.x;
    const int ng = t & 7, mg = (t >> 3) & 3, h = t >> 5;
    const int m0 = (blockIdx.x >> 3) * 8;
    const int n0 = (blockIdx.x & 7) * 64;
    float* As  = s;           // 4096
    float* Ws  = s + 4096;    // 4096
    float* red = s + 8192;    // 256*17 = 4352

    // stage A slice [8 rows x 512] transposed to As[k][row]
#pragma unroll
    for (int q = 0; q < 4; q++) {
        int i = t + q * NT;
        int row = i >> 7;          // 0..7
        int k4 = i & 127;
        float4 v = __ldcg((const float4*)&Ain[(m0 + row) * 512 + k4 * 4]);
        As[(k4 * 4 + 0) * 8 + row] = v.x;
        As[(k4 * 4 + 1) * 8 + row] = v.y;
        As[(k4 * 4 + 2) * 8 + row] = v.z;
        As[(k4 * 4 + 3) * 8 + row] = v.w;
    }

    float2 acc[2][4];
#pragma unroll
    for (int r = 0; r < 2; r++)
#pragma unroll
        for (int p = 0; p < 4; p++) acc[r][p] = make_float2(0.f, 0.f);

    for (int kt = 0; kt < 512; kt += 64) {
        __syncthreads();
        // stage W tile [64 k x 64 cols]
#pragma unroll
        for (int q = 0; q < 4; q++) {
            int i = t + q * NT;
            int row = i >> 4;      // 0..63
            int c4 = i & 15;
            float4 v = __ldg((const float4*)&W[(kt + row) * 512 + n0 + c4 * 4]);
            *(float4*)&Ws[row * 64 + c4 * 4] = v;
        }
        __syncthreads();
#pragma unroll
        for (int r8 = 0; r8 < 8; r8++) {
            int kk = kt + h * 8 + r8;
            float2 a = *(float2*)&As[kk * 8 + mg * 2];
            float4 w0 = *(float4*)&Ws[(kk - kt) * 64 + ng * 8];
            float4 w1 = *(float4*)&Ws[(kk - kt) * 64 + ng * 8 + 4];
            float2 ax = make_float2(a.x, a.x);
            float2 ay = make_float2(a.y, a.y);
            float2 wp0 = make_float2(w0.x, w0.y), wp1 = make_float2(w0.z, w0.w);
            float2 wp2 = make_float2(w1.x, w1.y), wp3 = make_float2(w1.z, w1.w);
            acc[0][0] = ffma2(ax, wp0, acc[0][0]);
            acc[0][1] = ffma2(ax, wp1, acc[0][1]);
            acc[0][2] = ffma2(ax, wp2, acc[0][2]);
            acc[0][3] = ffma2(ax, wp3, acc[0][3]);
            acc[1][0] = ffma2(ay, wp0, acc[1][0]);
            acc[1][1] = ffma2(ay, wp1, acc[1][1]);
            acc[1][2] = ffma2(ay, wp2, acc[1][2]);
            acc[1][3] = ffma2(ay, wp3, acc[1][3]);
        }
    }

    // reduce across h (8 partials)
    __syncthreads();
    float* my = &red[t * 17];
#pragma unroll
    for (int r = 0; r < 2; r++)
#pragma unroll
        for (int p = 0; p < 4; p++) {
            my[r * 8 + p * 2 + 0] = acc[r][p].x;
            my[r * 8 + p * 2 + 1] = acc[r][p].y;
        }
    __syncthreads();
#pragma unroll
    for (int s2 = 4; s2 >= 1; s2 >>= 1) {
        if (h < s2) {
            const float* other = &red[(t + s2 * 32) * 17];
#pragma unroll
            for (int i = 0; i < 16; i++) my[i] += other[i];
        }
        __syncthreads();
    }
    if (h == 0) {
#pragma unroll
        for (int r = 0; r < 2; r++) {
            int m = m0 + mg * 2 + r;
#pragma unroll
            for (int c = 0; c < 8; c++) {
                int n = n0 + ng * 8 + c;
                float v = my[r * 8 + c] + __ldg(&bias[n]);
                v = (v > 0.f) ? v : 0.01f * v;
                Aout[m * 512 + n] = v;
            }
        }
    }
}

// ---------------------------------------------------------------------------
// The persistent mega-kernel
// ---------------------------------------------------------------------------
__global__ __launch_bounds__(NT, 1)
void mega_kernel(const float* __restrict__ z,
                 const float* __restrict__ logP,
                 const float* __restrict__ hW0, const float* __restrict__ hb0,
                 const float* __restrict__ hW1, const float* __restrict__ hb1,
                 const float* __restrict__ hW2, const float* __restrict__ hb2,
                 const float* __restrict__ hWo, const float* __restrict__ hbo,
                 float* __restrict__ out)
{
    extern __shared__ float s[];
    const int t = threadIdx.x;
    const int bid = blockIdx.x;

    // ---------------- Phase 0: h0 = leaky(z @ hW0 + hb0), K=16 -------------
    if (bid < 128) {
        const int n0 = bid * 4;
        const int m = t & 127, cp = t >> 7;
        float2 acc = make_float2(0.f, 0.f);
#pragma unroll
        for (int k = 0; k < 16; k++) {
            float a = __ldg(&z[m * 16 + k]);
            float2 w = __ldg((const float2*)&hW0[k * 512 + n0 + cp * 2]);
            acc = ffma2(make_float2(a, a), w, acc);
        }
        float2 bb = __ldg((const float2*)&hb0[n0 + cp * 2]);
        float vx = acc.x + bb.x; vx = (vx > 0.f) ? vx : 0.01f * vx;
        float vy = acc.y + bb.y; vy = (vy > 0.f) ? vy : 0.01f * vy;
        *(float2*)&g_h0[m * 512 + n0 + cp * 2] = make_float2(vx, vy);
    }
    grid_barrier();

    // ---------------- Phases 1,2: hidden layers ----------------------------
    h_layer(g_h0, hW1, hb1, g_h1, s);
    grid_barrier();
    h_layer(g_h1, hW2, hb2, g_h2, s);
    grid_barrier();

    // ---------------- Phase 3: wab = h2 @ hWo + hbo ------------------------
    // All 133 blocks. BM=128 (full M), BN=64 per block, BK=16.
    // Threads: ng = t&7 (8 cols), mg = t>>3 (4 rows). acc 4x8 in f32x2.
    {
        const int ng = t & 7, mg = t >> 3;
        const int n0 = bid * 64;
        float* As = s;                 // [16][132] = 2112
        float* Bs = s + 16 * 132;      // [16][64]  = 1024

        float2 acc[4][4];
#pragma unroll
        for (int r = 0; r < 4; r++)
#pragma unroll
            for (int p = 0; p < 4; p++) acc[r][p] = make_float2(0.f, 0.f);

        for (int kt = 0; kt < 512; kt += 16) {
            __syncthreads();
            // A tile: 128 rows x 16 k, transposed
#pragma unroll
            for (int q = 0; q < 2; q++) {
                int i = t + q * NT;
                int m = i >> 2;        // 0..127
                int kq = i & 3;
                float4 v = __ldcg((const float4*)&g_h2[m * 512 + kt + kq * 4]);
                As[(kq * 4 + 0) * 132 + m] = v.x;
                As[(kq * 4 + 1) * 132 + m] = v.y;
                As[(kq * 4 + 2) * 132 + m] = v.z;
                As[(kq * 4 + 3) * 132 + m] = v.w;
            }
            // B tile: 16 k x 64 cols (float2, guarded; OUTS is even)
#pragma unroll
            for (int q = 0; q < 2; q++) {
                int i = t + q * NT;
                int row = i >> 5;      // 0..15
                int c2 = i & 31;
                int gc = n0 + c2 * 2;
                float2 v = make_float2(0.f, 0.f);
                if (gc + 2 <= OUTS)
                    v = __ldg((const float2*)&hWo[(size_t)(kt + row) * OUTS + gc]);
                *(float2*)&Bs[row * 64 + c2 * 2] = v;
            }
            __syncthreads();
#pragma unroll
            for (int kk = 0; kk < 16; kk++) {
                float4 a4 = *(float4*)&As[kk * 132 + mg * 4];
                float4 w0 = *(float4*)&Bs[kk * 64 + ng * 8];
                float4 w1 = *(float4*)&Bs[kk * 64 + ng * 8 + 4];
                float2 wp0 = make_float2(w0.x, w0.y), wp1 = make_float2(w0.z, w0.w);
                float2 wp2 = make_float2(w1.x, w1.y), wp3 = make_float2(w1.z, w1.w);
                float ar[4] = {a4.x, a4.y, a4.z, a4.w};
#pragma unroll
                for (int r = 0; r < 4; r++) {
                    float2 a2 = make_float2(ar[r], ar[r]);
                    acc[r][0] = ffma2(a2, wp0, acc[r][0]);
                    acc[r][1] = ffma2(a2, wp1, acc[r][1]);
                    acc[r][2] = ffma2(a2, wp2, acc[r][2]);
                    acc[r][3] = ffma2(a2, wp3, acc[r][3]);
                }
            }
        }
        // epilogue: + bias, store
#pragma unroll
        for (int r = 0; r < 4; r++) {
            int m = mg * 4 + r;
#pragma unroll
            for (int p = 0; p < 4; p++) {
                int n = n0 + ng * 8 + p * 2;
                if (n < OUTS) {
                    float2 bb = __ldg((const float2*)&hbo[n]);
                    float2 v = make_float2(acc[r][p].x + bb.x, acc[r][p].y + bb.y);
                    *(float2*)&g_wab[(size_t)m * OUTS + n] = v;
                }
            }
        }
    }
    grid_barrier();

    // ---------------- Phase 4: decoder -------------------------------------
    if (bid < 128) {
        float* s_w0 = s;
        float* s_W1 = s + 64;
        float* s_W2 = s + 4160;
        float* s_w3 = s + 8256;
        float* s_b1 = s + 8320;
        float* s_b2 = s + 8384;
        float* s_sc = s + 8448;
        float* s_x  = s + 8452;
        const float* __restrict__ src = g_wab + (size_t)bid * OUTS;

        if (t < 64) {
            s_w0[t] = __ldcg(&src[t]);
            s_b1[t] = __ldcg(&src[4161 + t]);
            s_b2[t] = __ldcg(&src[8321 + t]);
            s_w3[t] = __ldcg(&src[8385 + t]);
        }
        for (int i = t; i < 4096; i += NT) {
            s_W1[i] = __ldcg(&src[65 + i]);
            s_W2[i] = __ldcg(&src[4225 + i]);
        }
        if (t == 0) { s_sc[0] = __ldcg(&src[64]); s_sc[1] = __ldcg(&src[8449]); }
        __syncthreads();

        const int lane = t & 127;
        const int grp = t >> 7;        // 0..1
        const int j0 = grp * 32;
        const bool active = (lane < GSZ);
        float x_in = 0.f;
        if (active) x_in = __ldg(&logP[bid * GSZ + lane]) * (1.0f / 3.0f);
        const float b0 = s_sc[0];
        const float b3 = s_sc[1];

        if (active) {
#pragma unroll
            for (int jj = 0; jj < 32; jj++) {
                float v = 30.0f * fmaf(x_in, s_w0[j0 + jj], b0);
                s_x[(j0 + jj) * 128 + lane] = sinf(v);
            }
        }
        __syncthreads();

        float2 acc[16];

        // layer 1
        if (active) {
#pragma unroll
            for (int q = 0; q < 16; q++) acc[q] = *(float2*)&s_b1[j0 + q * 2];
#pragma unroll 4
            for (int i = 0; i < 64; i++) {
                float a = s_x[i * 128 + lane];
                float2 a2 = make_float2(a, a);
#pragma unroll
                for (int q = 0; q < 8; q++) {
                    float4 w = *(float4*)&s_W1[i * 64 + j0 + q * 4];
                    acc[q * 2 + 0] = ffma2(a2, make_float2(w.x, w.y), acc[q * 2 + 0]);
                    acc[q * 2 + 1] = ffma2(a2, make_float2(w.z, w.w), acc[q * 2 + 1]);
                }
            }
        }
        __syncthreads();
        if (active) {
#pragma unroll
            for (int q = 0; q < 16; q++) {
                s_x[(j0 + q * 2 + 0) * 128 + lane] = sinf(acc[q].x);
                s_x[(j0 + q * 2 + 1) * 128 + lane] = sinf(acc[q].y);
            }
        }
        __syncthreads();

        // layer 2
        if (active) {
#pragma unroll
            for (int q = 0; q < 16; q++) acc[q] = *(float2*)&s_b2[j0 + q * 2];
#pragma unroll 4
            for (int i = 0; i < 64; i++) {
                float a = s_x[i * 128 + lane];
                float2 a2 = make_float2(a, a);
#pragma unroll
                for (int q = 0; q < 8; q++) {
                    float4 w = *(float4*)&s_W2[i * 64 + j0 + q * 4];
                    acc[q * 2 + 0] = ffma2(a2, make_float2(w.x, w.y), acc[q * 2 + 0]);
                    acc[q * 2 + 1] = ffma2(a2, make_float2(w.z, w.w), acc[q * 2 + 1]);
                }
            }
        }
        __syncthreads();
        if (active) {
#pragma unroll
            for (int q = 0; q < 16; q++) {
                s_x[(j0 + q * 2 + 0) * 128 + lane] = sinf(acc[q].x);
                s_x[(j0 + q * 2 + 1) * 128 + lane] = sinf(acc[q].y);
            }
        }
        __syncthreads();

        // layer 3 (scalar out): group 0 reduces
        if (grp == 0 && active) {
            float o = b3;
#pragma unroll 8
            for (int i = 0; i < 64; i++)
                o = fmaf(s_x[i * 128 + lane], s_w3[i], o);
            out[bid * GSZ + lane] = fmaf(o, 500.0f, 1500.0f);
        }
    }
}

// ---------------------------------------------------------------------------
extern "C" void kernel_launch(void* const* d_in, const int* in_sizes, int n_in,
                              void* d_out, int out_size)
{
    const float* z    = (const float*)d_in[0];
    const float* logP = (const float*)d_in[1];
    const float* hW0  = (const float*)d_in[2];
    const float* hb0  = (const float*)d_in[3];
    const float* hW1  = (const float*)d_in[4];
    const float* hb1  = (const float*)d_in[5];
    const float* hW2  = (const float*)d_in[6];
    const float* hb2  = (const float*)d_in[7];
    const float* hWo  = (const float*)d_in[8];
    const float* hbo  = (const float*)d_in[9];
    float* out = (float*)d_out;

    const int smem_bytes = (8452 + 64 * 128) * (int)sizeof(float);  // 66576
    static int configured = 0;
    if (!configured) {
        cudaFuncSetAttribute(mega_kernel,
                             cudaFuncAttributeMaxDynamicSharedMemorySize, smem_bytes);
        configured = 1;
    }
    mega_kernel<<<NB, NT, smem_bytes>>>(z, logP, hW0, hb0, hW1, hb1,
                                        hW2, hb2, hWo, hbo, out);
}

// round 4
// speedup vs baseline: 1.4508x; 1.4508x over previous
#include <cuda_runtime.h>
#include <math.h>

#define LDIM   16
#define HLDIM  512
#define BSZ    128
#define GSZ    100
#define OUTS   8450   // 64 + 1 + 4096 + 64 + 4096 + 64 + 64 + 1

// Scratch (no cudaMalloc allowed)
__device__ float g_h0[BSZ * HLDIM];
__device__ float g_h1[BSZ * HLDIM];
__device__ float g_h2[BSZ * HLDIM];
__device__ float g_wab[BSZ * OUTS];
__device__ float g_part[4 * BSZ * OUTS];   // split-K partials (max: wab S=4)

// ---------------------------------------------------------------------------
// Packed fp32x2 FMA (Blackwell) — 2 exact fp32 MACs per issue slot
// ---------------------------------------------------------------------------
__device__ __forceinline__ float2 ffma2(float2 a, float2 b, float2 c) {
    float2 d;
    asm("{\n\t"
        ".reg .b64 A,B,C,D;\n\t"
        "mov.b64 A,{%2,%3};\n\t"
        "mov.b64 B,{%4,%5};\n\t"
        "mov.b64 C,{%6,%7};\n\t"
        "fma.rn.f32x2 D,A,B,C;\n\t"
        "mov.b64 {%0,%1},D;\n\t"
        "}"
        : "=f"(d.x), "=f"(d.y)
        : "f"(a.x), "f"(a.y), "f"(b.x), "f"(b.y), "f"(c.x), "f"(c.y));
    return d;
}

// ----------------------------------------------------------------------------
// Tiled fp32 GEMM (FFMA2 inner) with optional split-K.
// SPLITS==1: C = act(A@B + bias). SPLITS>1: raw partials to C[z][M][N].
// Requires TN even; K % (SPLITS*BK) == 0; N even (float2 B loads).
// ----------------------------------------------------------------------------
template<int BM, int BN, int BK, int TM, int TN, int ACT, int SPLITS>
__launch_bounds__((BM / TM) * (BN / TN))
__global__ void gemm_k(const float* __restrict__ A,
                       const float* __restrict__ B,
                       const float* __restrict__ bias,
                       float* __restrict__ C,
                       int M, int N, int K)
{
    constexpr int NT = (BM / TM) * (BN / TN);
    static_assert(TN % 2 == 0, "TN must be even");
    __shared__ float As[BK][BM + 4];
    __shared__ float Bs[BK][BN];

    const int bm = blockIdx.y * BM;
    const int bn = blockIdx.x * BN;
    const int tid = threadIdx.x;
    const int tc = (tid % (BN / TN)) * TN;
    const int tr = (tid / (BN / TN)) * TM;

    const int Kc = K / SPLITS;
    const int kbase = blockIdx.z * Kc;

    float2 acc[TM][TN / 2];
#pragma unroll
    for (int i = 0; i < TM; i++)
#pragma unroll
        for (int j = 0; j < TN / 2; j++) acc[i][j] = make_float2(0.f, 0.f);

    for (int k0 = 0; k0 < Kc; k0 += BK) {
        // A tile: float4 global loads (rows 16B aligned; K % 4 == 0)
#pragma unroll
        for (int idx = tid; idx < BM * (BK / 4); idx += NT) {
            int m = idx / (BK / 4);
            int kq = idx % (BK / 4);
            float4 v = *(const float4*)&A[(size_t)(bm + m) * K + kbase + k0 + kq * 4];
            As[kq * 4 + 0][m] = v.x;
            As[kq * 4 + 1][m] = v.y;
            As[kq * 4 + 2][m] = v.z;
            As[kq * 4 + 3][m] = v.w;
        }
        // B tile: float2 coalesced loads (N even), guarded on right edge
#pragma unroll
        for (int idx = tid; idx < BK * (BN / 2); idx += NT) {
            int kk = idx / (BN / 2);
            int c2 = idx % (BN / 2);
            int gc = bn + c2 * 2;
            float2 v = make_float2(0.f, 0.f);
            if (gc + 2 <= N)
                v = *(const float2*)&B[(size_t)(kbase + k0 + kk) * N + gc];
            *(float2*)&Bs[kk][c2 * 2] = v;
        }
        __syncthreads();

#pragma unroll
        for (int kk = 0; kk < BK; kk++) {
            float av[TM];
            float2 bv[TN / 2];
            if constexpr (TM % 4 == 0) {
#pragma unroll
                for (int i = 0; i < TM; i += 4) {
                    float4 v = *(const float4*)&As[kk][tr + i];
                    av[i] = v.x; av[i + 1] = v.y; av[i + 2] = v.z; av[i + 3] = v.w;
                }
            } else {
#pragma unroll
                for (int i = 0; i < TM; i++) av[i] = As[kk][tr + i];
            }
            if constexpr (TN % 4 == 0) {
#pragma unroll
                for (int j = 0; j < TN / 4; j++) {
                    float4 v = *(const float4*)&Bs[kk][tc + j * 4];
                    bv[j * 2 + 0] = make_float2(v.x, v.y);
                    bv[j * 2 + 1] = make_float2(v.z, v.w);
                }
            } else {
#pragma unroll
                for (int j = 0; j < TN / 2; j++)
                    bv[j] = *(const float2*)&Bs[kk][tc + j * 2];
            }
#pragma unroll
            for (int i = 0; i < TM; i++) {
                float2 a2 = make_float2(av[i], av[i]);
#pragma unroll
                for (int j = 0; j < TN / 2; j++)
                    acc[i][j] = ffma2(a2, bv[j], acc[i][j]);
            }
        }
        __syncthreads();
    }

    if constexpr (SPLITS == 1) {
#pragma unroll
        for (int i = 0; i < TM; i++) {
            int gm = bm + tr + i;
#pragma unroll
            for (int j = 0; j < TN / 2; j++) {
#pragma unroll
                for (int h = 0; h < 2; h++) {
                    int gn = bn + tc + j * 2 + h;
                    if (gn < N) {
                        float v = ((h == 0) ? acc[i][j].x : acc[i][j].y) + bias[gn];
                        if (ACT) v = (v > 0.0f) ? v : 0.01f * v;
                        C[(size_t)gm * N + gn] = v;
                    }
                }
            }
        }
    } else {
        float* __restrict__ P = C + (size_t)blockIdx.z * M * N;
#pragma unroll
        for (int i = 0; i < TM; i++) {
            int gm = bm + tr + i;
#pragma unroll
            for (int j = 0; j < TN / 2; j++) {
                int gn = bn + tc + j * 2;
                if (gn + 2 <= N) {
                    *(float2*)&P[(size_t)gm * N + gn] = acc[i][j];
                } else if (gn < N) {
                    P[(size_t)gm * N + gn] = acc[i][j].x;
                }
            }
        }
    }
}

// ----------------------------------------------------------------------------
// Split-K reduce + bias + optional leaky relu
// ----------------------------------------------------------------------------
template<int ACT, int SPLITS>
__global__ void reduce_bias(const float* __restrict__ P,
                            const float* __restrict__ bias,
                            float* __restrict__ C, int M, int N)
{
    int i = blockIdx.x * blockDim.x + threadIdx.x;
    int MN = M * N;
    if (i >= MN) return;
    float s = 0.0f;
#pragma unroll
    for (int z = 0; z < SPLITS; z++) s += P[(size_t)z * MN + i];
    s += bias[i % N];
    if (ACT) s = (s > 0.0f) ? s : 0.01f * s;
    C[i] = s;
}

// ----------------------------------------------------------------------------
// Decoder: one block per b, 512 threads = 4 j-groups x 128 g-lanes.
// ----------------------------------------------------------------------------
#define DEC_NT 512
#define DEC_SMEM_FLOATS (8452 + 64 * 128)

__global__ __launch_bounds__(DEC_NT)
void decoder_kernel(const float* __restrict__ logP,
                    const float* __restrict__ wab,
                    float* __restrict__ out)
{
    extern __shared__ float s[];
    float* s_w0 = s;
    float* s_W1 = s + 64;
    float* s_W2 = s + 4160;
    float* s_w3 = s + 8256;
    float* s_b1 = s + 8320;
    float* s_b2 = s + 8384;
    float* s_sc = s + 8448;
    float* s_x  = s + 8452;

    const int b = blockIdx.x;
    const int tid = threadIdx.x;
    const int lane = tid & 127;
    const int grp = tid >> 7;          // 0..3
    const int j0 = grp * 16;
    const float* __restrict__ src = wab + (size_t)b * OUTS;

    if (tid < 64) {
        s_w0[tid] = src[tid];
        s_b1[tid] = src[4161 + tid];
        s_b2[tid] = src[8321 + tid];
        s_w3[tid] = src[8385 + tid];
    }
    for (int i = tid; i < 4096; i += DEC_NT) {
        s_W1[i] = src[65 + i];
        s_W2[i] = src[4225 + i];
    }
    if (tid == 0) { s_sc[0] = src[64]; s_sc[1] = src[8449]; }
    __syncthreads();

    const bool active = (lane < GSZ);
    float x_in = 0.0f;
    if (active) x_in = logP[b * GSZ + lane] * (1.0f / 3.0f);
    const float b0 = s_sc[0];
    const float b3 = s_sc[1];

    if (active) {
#pragma unroll
        for (int jj = 0; jj < 16; jj++) {
            float v = 30.0f * fmaf(x_in, s_w0[j0 + jj], b0);
            s_x[(j0 + jj) * 128 + lane] = sinf(v);
        }
    }
    __syncthreads();

    float2 acc[8];

    // layer 1
    if (active) {
#pragma unroll
        for (int q = 0; q < 8; q++) acc[q] = *(float2*)&s_b1[j0 + q * 2];
#pragma unroll 8
        for (int i = 0; i < 64; i++) {
            float a = s_x[i * 128 + lane];
            float2 a2 = make_float2(a, a);
#pragma unroll
            for (int q = 0; q < 4; q++) {
                float4 w = *(float4*)&s_W1[i * 64 + j0 + q * 4];
                acc[q * 2 + 0] = ffma2(a2, make_float2(w.x, w.y), acc[q * 2 + 0]);
                acc[q * 2 + 1] = ffma2(a2, make_float2(w.z, w.w), acc[q * 2 + 1]);
            }
        }
    }
    __syncthreads();
    if (active) {
#pragma unroll
        for (int q = 0; q < 8; q++) {
            s_x[(j0 + q * 2 + 0) * 128 + lane] = sinf(acc[q].x);
            s_x[(j0 + q * 2 + 1) * 128 + lane] = sinf(acc[q].y);
        }
    }
    __syncthreads();

    // layer 2
    if (active) {
#pragma unroll
        for (int q = 0; q < 8; q++) acc[q] = *(float2*)&s_b2[j0 + q * 2];
#pragma unroll 8
        for (int i = 0; i < 64; i++) {
            float a = s_x[i * 128 + lane];
            float2 a2 = make_float2(a, a);
#pragma unroll
            for (int q = 0; q < 4; q++) {
                float4 w = *(float4*)&s_W2[i * 64 + j0 + q * 4];
                acc[q * 2 + 0] = ffma2(a2, make_float2(w.x, w.y), acc[q * 2 + 0]);
                acc[q * 2 + 1] = ffma2(a2, make_float2(w.z, w.w), acc[q * 2 + 1]);
            }
        }
    }
    __syncthreads();
    if (active) {
#pragma unroll
        for (int q = 0; q < 8; q++) {
            s_x[(j0 + q * 2 + 0) * 128 + lane] = sinf(acc[q].x);
            s_x[(j0 + q * 2 + 1) * 128 + lane] = sinf(acc[q].y);
        }
    }
    __syncthreads();

    // layer 3 (scalar out): group 0 reduces
    if (grp == 0 && active) {
        float o = b3;
#pragma unroll 8
        for (int i = 0; i < 64; i++)
            o = fmaf(s_x[i * 128 + lane], s_w3[i], o);
        out[b * GSZ + lane] = fmaf(o, 500.0f, 1500.0f);
    }
}

// ----------------------------------------------------------------------------
extern "C" void kernel_launch(void* const* d_in, const int* in_sizes, int n_in,
                              void* d_out, int out_size)
{
    const float* z    = (const float*)d_in[0];
    const float* logP = (const float*)d_in[1];
    const float* hW0  = (const float*)d_in[2];
    const float* hb0  = (const float*)d_in[3];
    const float* hW1  = (const float*)d_in[4];
    const float* hb1  = (const float*)d_in[5];
    const float* hW2  = (const float*)d_in[6];
    const float* hb2  = (const float*)d_in[7];
    const float* hWo  = (const float*)d_in[8];
    const float* hbo  = (const float*)d_in[9];
    float* out = (float*)d_out;

    float *h0p, *h1p, *h2p, *wabp, *partp;
    cudaGetSymbolAddress((void**)&h0p, g_h0);
    cudaGetSymbolAddress((void**)&h1p, g_h1);
    cudaGetSymbolAddress((void**)&h2p, g_h2);
    cudaGetSymbolAddress((void**)&wabp, g_wab);
    cudaGetSymbolAddress((void**)&partp, g_part);

    // h0: 128x512x16, direct with bias+leaky
    gemm_k<32, 64, 16, 2, 4, 1, 1><<<dim3(HLDIM / 64, BSZ / 32, 1), 256>>>(
        z, hW0, hb0, h0p, BSZ, HLDIM, LDIM);

    // h1: 128x512x512, split-K x8
    gemm_k<64, 64, 16, 4, 4, 0, 8><<<dim3(HLDIM / 64, BSZ / 64, 8), 256>>>(
        h0p, hW1, hb1, partp, BSZ, HLDIM, HLDIM);
    reduce_bias<1, 8><<<(BSZ * HLDIM + 255) / 256, 256>>>(
        partp, hb1, h1p, BSZ, HLDIM);

    // h2
    gemm_k<64, 64, 16, 4, 4, 0, 8><<<dim3(HLDIM / 64, BSZ / 64, 8), 256>>>(
        h1p, hW2, hb2, partp, BSZ, HLDIM, HLDIM);
    reduce_bias<1, 8><<<(BSZ * HLDIM + 255) / 256, 256>>>(
        partp, hb2, h2p, BSZ, HLDIM);

    // wab: 128x8450x512, split-K x4, 128x128 tile, 8x8 FFMA2 register tile
    gemm_k<128, 128, 16, 8, 8, 0, 4><<<dim3((OUTS + 127) / 128, 1, 4), 256>>>(
        h2p, hWo, hbo, partp, BSZ, OUTS, HLDIM);
    reduce_bias<0, 4><<<(BSZ * OUTS + 255) / 256, 256>>>(
        partp, hbo, wabp, BSZ, OUTS);

    // decoder
    const int smem_bytes = DEC_SMEM_FLOATS * (int)sizeof(float);
    static int configured = 0;
    if (!configured) {
        cudaFuncSetAttribute(decoder_kernel,
                             cudaFuncAttributeMaxDynamicSharedMemorySize, smem_bytes);
        configured = 1;
    }
    decoder_kernel<<<BSZ, DEC_NT, smem_bytes>>>(logP, wabp, out);
}

// round 5
// speedup vs baseline: 1.4898x; 1.0269x over previous
#include <cuda_runtime.h>
#include <math.h>

#define LDIM   16
#define HLDIM  512
#define BSZ    128
#define GSZ    100
#define OUTS   8450   // 64 + 1 + 4096 + 64 + 4096 + 64 + 64 + 1

// Scratch (no cudaMalloc allowed)
__device__ float g_h0[BSZ * HLDIM];
__device__ float g_h1[BSZ * HLDIM];
__device__ float g_h2[BSZ * HLDIM];
__device__ float g_part[4 * BSZ * OUTS];   // split-K partials (max: wab S=4)

// ---------------------------------------------------------------------------
// Packed fp32x2 FMA (Blackwell) — 2 exact fp32 MACs per issue slot
// ---------------------------------------------------------------------------
__device__ __forceinline__ float2 ffma2(float2 a, float2 b, float2 c) {
    float2 d;
    asm("{\n\t"
        ".reg .b64 A,B,C,D;\n\t"
        "mov.b64 A,{%2,%3};\n\t"
        "mov.b64 B,{%4,%5};\n\t"
        "mov.b64 C,{%6,%7};\n\t"
        "fma.rn.f32x2 D,A,B,C;\n\t"
        "mov.b64 {%0,%1},D;\n\t"
        "}"
        : "=f"(d.x), "=f"(d.y)
        : "f"(a.x), "f"(a.y), "f"(b.x), "f"(b.y), "f"(c.x), "f"(c.y));
    return d;
}

// ----------------------------------------------------------------------------
// Double-buffered fp32 GEMM (FFMA2 inner) with optional split-K.
// Register-prefetches the next k-tile during compute to hide L2 latency.
// SPLITS==1: C = act(A@B + bias). SPLITS>1: raw partials to C[z][M][N].
// ----------------------------------------------------------------------------
template<int BM, int BN, int BK, int TM, int TN, int ACT, int SPLITS>
__launch_bounds__((BM / TM) * (BN / TN))
__global__ void gemm_db(const float* __restrict__ A,
                        const float* __restrict__ B,
                        const float* __restrict__ bias,
                        float* __restrict__ C,
                        int M, int N, int K)
{
    constexpr int NT = (BM / TM) * (BN / TN);
    constexpr int APT = (BM * BK) / (4 * NT);   // float4 A loads / thread
    constexpr int BPT = (BK * BN) / (2 * NT);   // float2 B loads / thread
    static_assert(APT >= 1 && (BM * BK) % (4 * NT) == 0, "APT");
    static_assert(BPT >= 1 && (BK * BN) % (2 * NT) == 0, "BPT");
    static_assert(TN % 2 == 0, "TN even");

    __shared__ float As[BK][BM + 4];
    __shared__ float Bs[BK][BN];

    const int bm = blockIdx.y * BM;
    const int bn = blockIdx.x * BN;
    const int tid = threadIdx.x;
    const int tc = (tid % (BN / TN)) * TN;
    const int tr = (tid / (BN / TN)) * TM;

    const int Kc = K / SPLITS;
    const int kbase = blockIdx.z * Kc;

    float4 aReg[APT];
    float2 bReg[BPT];

    auto load_tiles = [&](int k0) {
#pragma unroll
        for (int q = 0; q < APT; q++) {
            int idx = tid + q * NT;
            int m = idx / (BK / 4);
            int kq = idx % (BK / 4);
            aReg[q] = *(const float4*)&A[(size_t)(bm + m) * K + kbase + k0 + kq * 4];
        }
#pragma unroll
        for (int q = 0; q < BPT; q++) {
            int idx = tid + q * NT;
            int kk = idx / (BN / 2);
            int c2 = idx % (BN / 2);
            int gc = bn + c2 * 2;
            float2 v = make_float2(0.f, 0.f);
            if (gc + 2 <= N)
                v = *(const float2*)&B[(size_t)(kbase + k0 + kk) * N + gc];
            bReg[q] = v;
        }
    };
    auto store_tiles = [&]() {
#pragma unroll
        for (int q = 0; q < APT; q++) {
            int idx = tid + q * NT;
            int m = idx / (BK / 4);
            int kq = idx % (BK / 4);
            As[kq * 4 + 0][m] = aReg[q].x;
            As[kq * 4 + 1][m] = aReg[q].y;
            As[kq * 4 + 2][m] = aReg[q].z;
            As[kq * 4 + 3][m] = aReg[q].w;
        }
#pragma unroll
        for (int q = 0; q < BPT; q++) {
            int idx = tid + q * NT;
            int kk = idx / (BN / 2);
            int c2 = idx % (BN / 2);
            *(float2*)&Bs[kk][c2 * 2] = bReg[q];
        }
    };

    float2 acc[TM][TN / 2];
#pragma unroll
    for (int i = 0; i < TM; i++)
#pragma unroll
        for (int j = 0; j < TN / 2; j++) acc[i][j] = make_float2(0.f, 0.f);

    load_tiles(0);
    for (int k0 = 0; k0 < Kc; k0 += BK) {
        store_tiles();
        __syncthreads();
        if (k0 + BK < Kc) load_tiles(k0 + BK);   // prefetch next tile

#pragma unroll
        for (int kk = 0; kk < BK; kk++) {
            float av[TM];
            float2 bv[TN / 2];
            if constexpr (TM % 4 == 0) {
#pragma unroll
                for (int i = 0; i < TM; i += 4) {
                    float4 v = *(const float4*)&As[kk][tr + i];
                    av[i] = v.x; av[i + 1] = v.y; av[i + 2] = v.z; av[i + 3] = v.w;
                }
            } else if constexpr (TM % 2 == 0) {
#pragma unroll
                for (int i = 0; i < TM; i += 2) {
                    float2 v = *(const float2*)&As[kk][tr + i];
                    av[i] = v.x; av[i + 1] = v.y;
                }
            } else {
#pragma unroll
                for (int i = 0; i < TM; i++) av[i] = As[kk][tr + i];
            }
            if constexpr (TN % 4 == 0) {
#pragma unroll
                for (int j = 0; j < TN / 4; j++) {
                    float4 v = *(const float4*)&Bs[kk][tc + j * 4];
                    bv[j * 2 + 0] = make_float2(v.x, v.y);
                    bv[j * 2 + 1] = make_float2(v.z, v.w);
                }
            } else {
#pragma unroll
                for (int j = 0; j < TN / 2; j++)
                    bv[j] = *(const float2*)&Bs[kk][tc + j * 2];
            }
#pragma unroll
            for (int i = 0; i < TM; i++) {
                float2 a2 = make_float2(av[i], av[i]);
#pragma unroll
                for (int j = 0; j < TN / 2; j++)
                    acc[i][j] = ffma2(a2, bv[j], acc[i][j]);
            }
        }
        __syncthreads();
    }

    if constexpr (SPLITS == 1) {
#pragma unroll
        for (int i = 0; i < TM; i++) {
            int gm = bm + tr + i;
#pragma unroll
            for (int j = 0; j < TN / 2; j++) {
#pragma unroll
                for (int h = 0; h < 2; h++) {
                    int gn = bn + tc + j * 2 + h;
                    if (gn < N) {
                        float v = ((h == 0) ? acc[i][j].x : acc[i][j].y) + bias[gn];
                        if (ACT) v = (v > 0.0f) ? v : 0.01f * v;
                        C[(size_t)gm * N + gn] = v;
                    }
                }
            }
        }
    } else {
        float* __restrict__ P = C + (size_t)blockIdx.z * M * N;
#pragma unroll
        for (int i = 0; i < TM; i++) {
            int gm = bm + tr + i;
#pragma unroll
            for (int j = 0; j < TN / 2; j++) {
                int gn = bn + tc + j * 2;
                if (gn + 2 <= N) {
                    *(float2*)&P[(size_t)gm * N + gn] = acc[i][j];
                } else if (gn < N) {
                    P[(size_t)gm * N + gn] = acc[i][j].x;
                }
            }
        }
    }
}

// ----------------------------------------------------------------------------
// h0: h0[128,512] = leaky(z[128,16] @ hW0[16,512] + hb0). Grid 128 x 256 thr.
// ----------------------------------------------------------------------------
__global__ __launch_bounds__(256)
void h0_kernel(const float* __restrict__ z,
               const float* __restrict__ hW0,
               const float* __restrict__ hb0,
               float* __restrict__ h0)
{
    const int t = threadIdx.x;
    const int n0 = blockIdx.x * 4 + (t >> 7) * 2;
    const int m = t & 127;
    float2 acc = make_float2(0.f, 0.f);
#pragma unroll
    for (int k = 0; k < 16; k++) {
        float a = __ldg(&z[m * 16 + k]);
        float2 w = __ldg((const float2*)&hW0[k * 512 + n0]);
        acc = ffma2(make_float2(a, a), w, acc);
    }
    float2 bb = __ldg((const float2*)&hb0[n0]);
    float vx = acc.x + bb.x; vx = (vx > 0.f) ? vx : 0.01f * vx;
    float vy = acc.y + bb.y; vy = (vy > 0.f) ? vy : 0.01f * vy;
    *(float2*)&h0[m * 512 + n0] = make_float2(vx, vy);
}

// ----------------------------------------------------------------------------
// Split-K reduce + bias + leaky (h1/h2 only)
// ----------------------------------------------------------------------------
template<int ACT, int SPLITS>
__global__ void reduce_bias(const float* __restrict__ P,
                            const float* __restrict__ bias,
                            float* __restrict__ C, int M, int N)
{
    int i = blockIdx.x * blockDim.x + threadIdx.x;
    int MN = M * N;
    if (i >= MN) return;
    float s = 0.0f;
#pragma unroll
    for (int z = 0; z < SPLITS; z++) s += P[(size_t)z * MN + i];
    s += bias[i % N];
    if (ACT) s = (s > 0.0f) ? s : 0.01f * s;
    C[i] = s;
}

// ----------------------------------------------------------------------------
// Decoder with fused wab split-K reduce: stages sum(4 partials)+hbo into smem,
// repacks to aligned weight regions, then runs the sin-MLP.
// One block per b, 512 threads = 4 j-groups x 128 g-lanes.
// smem floats: s_row[8452] | s_wgt[8452] | s_x[64*128]
// ----------------------------------------------------------------------------
#define DEC_NT 512
#define DEC_SMEM_FLOATS (8452 + 8452 + 64 * 128)

__global__ __launch_bounds__(DEC_NT)
void decoder_kernel(const float* __restrict__ logP,
                    const float* __restrict__ part,
                    const float* __restrict__ hbo,
                    float* __restrict__ out)
{
    extern __shared__ float s[];
    float* s_row = s;             // raw wab row (8450 used)
    float* s_wgt = s + 8452;      // aligned: w0[64] W1[4096]@64 W2[4096]@4160... 
    float* s_x   = s + 8452 + 8452;

    float* s_w0 = s_wgt;
    float* s_W1 = s_wgt + 64;
    float* s_W2 = s_wgt + 4160;
    float* s_w3 = s_wgt + 8256;
    float* s_b1 = s_wgt + 8320;
    float* s_b2 = s_wgt + 8384;
    float* s_sc = s_wgt + 8448;

    const int b = blockIdx.x;
    const int tid = threadIdx.x;

    // stage: wab_row[i] = sum_z part[z][b][i] + hbo[i]   (all float2)
    {
        const float2* bias2 = (const float2*)hbo;
        const float2* p0 = (const float2*)(part + (size_t)b * OUTS);
        const size_t zs = (size_t)BSZ * OUTS / 2;
        float2* row2 = (float2*)s_row;
        for (int i = tid; i < OUTS / 2; i += DEC_NT) {
            float2 a = bias2[i];
            float2 v0 = p0[i];
            float2 v1 = p0[i + zs];
            float2 v2 = p0[i + 2 * zs];
            float2 v3 = p0[i + 3 * zs];
            a.x += (v0.x + v1.x) + (v2.x + v3.x);
            a.y += (v0.y + v1.y) + (v2.y + v3.y);
            row2[i] = a;
        }
    }
    __syncthreads();

    // repack to aligned regions
    if (tid < 64) {
        s_w0[tid] = s_row[tid];
        s_b1[tid] = s_row[4161 + tid];
        s_b2[tid] = s_row[8321 + tid];
        s_w3[tid] = s_row[8385 + tid];
    }
    for (int i = tid; i < 4096; i += DEC_NT) {
        s_W1[i] = s_row[65 + i];
        s_W2[i] = s_row[4225 + i];
    }
    if (tid == 0) { s_sc[0] = s_row[64]; s_sc[1] = s_row[8449]; }
    __syncthreads();

    const int lane = tid & 127;
    const int grp = tid >> 7;          // 0..3
    const int j0 = grp * 16;
    const bool active = (lane < GSZ);
    float x_in = 0.0f;
    if (active) x_in = logP[b * GSZ + lane] * (1.0f / 3.0f);
    const float b0 = s_sc[0];
    const float b3 = s_sc[1];

    if (active) {
#pragma unroll
        for (int jj = 0; jj < 16; jj++) {
            float v = 30.0f * fmaf(x_in, s_w0[j0 + jj], b0);
            s_x[(j0 + jj) * 128 + lane] = sinf(v);
        }
    }
    __syncthreads();

    float2 acc[8];

    // layer 1
    if (active) {
#pragma unroll
        for (int q = 0; q < 8; q++) acc[q] = *(float2*)&s_b1[j0 + q * 2];
#pragma unroll 8
        for (int i = 0; i < 64; i++) {
            float a = s_x[i * 128 + lane];
            float2 a2 = make_float2(a, a);
#pragma unroll
            for (int q = 0; q < 4; q++) {
                float4 w = *(float4*)&s_W1[i * 64 + j0 + q * 4];
                acc[q * 2 + 0] = ffma2(a2, make_float2(w.x, w.y), acc[q * 2 + 0]);
                acc[q * 2 + 1] = ffma2(a2, make_float2(w.z, w.w), acc[q * 2 + 1]);
            }
        }
    }
    __syncthreads();
    if (active) {
#pragma unroll
        for (int q = 0; q < 8; q++) {
            s_x[(j0 + q * 2 + 0) * 128 + lane] = sinf(acc[q].x);
            s_x[(j0 + q * 2 + 1) * 128 + lane] = sinf(acc[q].y);
        }
    }
    __syncthreads();

    // layer 2
    if (active) {
#pragma unroll
        for (int q = 0; q < 8; q++) acc[q] = *(float2*)&s_b2[j0 + q * 2];
#pragma unroll 8
        for (int i = 0; i < 64; i++) {
            float a = s_x[i * 128 + lane];
            float2 a2 = make_float2(a, a);
#pragma unroll
            for (int q = 0; q < 4; q++) {
                float4 w = *(float4*)&s_W2[i * 64 + j0 + q * 4];
                acc[q * 2 + 0] = ffma2(a2, make_float2(w.x, w.y), acc[q * 2 + 0]);
                acc[q * 2 + 1] = ffma2(a2, make_float2(w.z, w.w), acc[q * 2 + 1]);
            }
        }
    }
    __syncthreads();
    if (active) {
#pragma unroll
        for (int q = 0; q < 8; q++) {
            s_x[(j0 + q * 2 + 0) * 128 + lane] = sinf(acc[q].x);
            s_x[(j0 + q * 2 + 1) * 128 + lane] = sinf(acc[q].y);
        }
    }
    __syncthreads();

    // layer 3 (scalar out): group 0 reduces
    if (grp == 0 && active) {
        float o = b3;
#pragma unroll 8
        for (int i = 0; i < 64; i++)
            o = fmaf(s_x[i * 128 + lane], s_w3[i], o);
        out[b * GSZ + lane] = fmaf(o, 500.0f, 1500.0f);
    }
}

// ----------------------------------------------------------------------------
extern "C" void kernel_launch(void* const* d_in, const int* in_sizes, int n_in,
                              void* d_out, int out_size)
{
    const float* z    = (const float*)d_in[0];
    const float* logP = (const float*)d_in[1];
    const float* hW0  = (const float*)d_in[2];
    const float* hb0  = (const float*)d_in[3];
    const float* hW1  = (const float*)d_in[4];
    const float* hb1  = (const float*)d_in[5];
    const float* hW2  = (const float*)d_in[6];
    const float* hb2  = (const float*)d_in[7];
    const float* hWo  = (const float*)d_in[8];
    const float* hbo  = (const float*)d_in[9];
    float* out = (float*)d_out;

    float *h0p, *h1p, *h2p, *partp;
    cudaGetSymbolAddress((void**)&h0p, g_h0);
    cudaGetSymbolAddress((void**)&h1p, g_h1);
    cudaGetSymbolAddress((void**)&h2p, g_h2);
    cudaGetSymbolAddress((void**)&partp, g_part);

    // h0: 128x512x16 (dedicated kernel, 128 CTAs)
    h0_kernel<<<128, 256>>>(z, hW0, hb0, h0p);

    // h1: 128x512x512, 32x64 tiles, split-K x8 -> 256 CTAs, double-buffered
    gemm_db<32, 64, 32, 2, 4, 0, 8><<<dim3(HLDIM / 64, BSZ / 32, 8), 256>>>(
        h0p, hW1, hb1, partp, BSZ, HLDIM, HLDIM);
    reduce_bias<1, 8><<<(BSZ * HLDIM + 255) / 256, 256>>>(
        partp, hb1, h1p, BSZ, HLDIM);

    // h2
    gemm_db<32, 64, 32, 2, 4, 0, 8><<<dim3(HLDIM / 64, BSZ / 32, 8), 256>>>(
        h1p, hW2, hb2, partp, BSZ, HLDIM, HLDIM);
    reduce_bias<1, 8><<<(BSZ * HLDIM + 255) / 256, 256>>>(
        partp, hb2, h2p, BSZ, HLDIM);

    // wab: 128x8450x512, 128x128 tile, split-K x4 -> 268 CTAs, double-buffered
    // (partials left in g_part; decoder fuses the reduce + bias)
    gemm_db<128, 128, 16, 8, 8, 0, 4><<<dim3((OUTS + 127) / 128, 1, 4), 256>>>(
        h2p, hWo, hbo, partp, BSZ, OUTS, HLDIM);

    // decoder (fused wab reduce)
    const int smem_bytes = DEC_SMEM_FLOATS * (int)sizeof(float);
    static int configured = 0;
    if (!configured) {
        cudaFuncSetAttribute(decoder_kernel,
                             cudaFuncAttributeMaxDynamicSharedMemorySize, smem_bytes);
        configured = 1;
    }
    decoder_kernel<<<BSZ, DEC_NT, smem_bytes>>>(logP, partp, hbo, out);
}

// round 6
// speedup vs baseline: 1.6564x; 1.1119x over previous
#include <cuda_runtime.h>
#include <math.h>

#define LDIM   16
#define HLDIM  512
#define BSZ    128
#define GSZ    100
#define OUTS   8450   // 64 + 1 + 4096 + 64 + 4096 + 64 + 64 + 1

// Scratch (no cudaMalloc allowed)
__device__ float g_h0[BSZ * HLDIM];
__device__ float g_h1[BSZ * HLDIM];
__device__ float g_h2[BSZ * HLDIM];
__device__ float g_part[8 * BSZ * HLDIM > 2 * BSZ * OUTS ? 8 * BSZ * HLDIM
                                                         : 2 * BSZ * OUTS];

// ---------------------------------------------------------------------------
// Packed fp32x2 FMA (Blackwell) — 2 exact fp32 MACs per issue slot
// ---------------------------------------------------------------------------
__device__ __forceinline__ float2 ffma2(float2 a, float2 b, float2 c) {
    float2 d;
    asm("{\n\t"
        ".reg .b64 A,B,C,D;\n\t"
        "mov.b64 A,{%2,%3};\n\t"
        "mov.b64 B,{%4,%5};\n\t"
        "mov.b64 C,{%6,%7};\n\t"
        "fma.rn.f32x2 D,A,B,C;\n\t"
        "mov.b64 {%0,%1},D;\n\t"
        "}"
        : "=f"(d.x), "=f"(d.y)
        : "f"(a.x), "f"(a.y), "f"(b.x), "f"(b.y), "f"(c.x), "f"(c.y));
    return d;
}

// HW-accurate fast sin: explicit range reduction to [-pi,pi], then MUFU sin.
__device__ __forceinline__ float fast_sin(float x) {
    float k = rintf(x * 0.15915494309189535f);       // x / (2*pi)
    float r = fmaf(k, -6.283185307179586f, x);       // x - k*2*pi
    return __sinf(r);
}

// ----------------------------------------------------------------------------
// Double-buffered fp32 GEMM (FFMA2 inner) with optional split-K.
// SPLITS==1: C = act(A@B + bias). SPLITS>1: raw partials to C[z][M][N].
// ----------------------------------------------------------------------------
template<int BM, int BN, int BK, int TM, int TN, int ACT, int SPLITS>
__launch_bounds__((BM / TM) * (BN / TN))
__global__ void gemm_db(const float* __restrict__ A,
                        const float* __restrict__ B,
                        const float* __restrict__ bias,
                        float* __restrict__ C,
                        int M, int N, int K)
{
    constexpr int NT = (BM / TM) * (BN / TN);
    constexpr int APT = (BM * BK) / (4 * NT);
    constexpr int BPT = (BK * BN) / (2 * NT);
    static_assert(APT >= 1 && (BM * BK) % (4 * NT) == 0, "APT");
    static_assert(BPT >= 1 && (BK * BN) % (2 * NT) == 0, "BPT");
    static_assert(TN % 2 == 0, "TN even");

    __shared__ float As[BK][BM + 4];
    __shared__ float Bs[BK][BN];

    const int bm = blockIdx.y * BM;
    const int bn = blockIdx.x * BN;
    const int tid = threadIdx.x;
    const int tc = (tid % (BN / TN)) * TN;
    const int tr = (tid / (BN / TN)) * TM;

    const int Kc = K / SPLITS;
    const int kbase = blockIdx.z * Kc;

    float4 aReg[APT];
    float2 bReg[BPT];

    auto load_tiles = [&](int k0) {
#pragma unroll
        for (int q = 0; q < APT; q++) {
            int idx = tid + q * NT;
            int m = idx / (BK / 4);
            int kq = idx % (BK / 4);
            aReg[q] = *(const float4*)&A[(size_t)(bm + m) * K + kbase + k0 + kq * 4];
        }
#pragma unroll
        for (int q = 0; q < BPT; q++) {
            int idx = tid + q * NT;
            int kk = idx / (BN / 2);
            int c2 = idx % (BN / 2);
            int gc = bn + c2 * 2;
            float2 v = make_float2(0.f, 0.f);
            if (gc + 2 <= N)
                v = *(const float2*)&B[(size_t)(kbase + k0 + kk) * N + gc];
            bReg[q] = v;
        }
    };
    auto store_tiles = [&]() {
#pragma unroll
        for (int q = 0; q < APT; q++) {
            int idx = tid + q * NT;
            int m = idx / (BK / 4);
            int kq = idx % (BK / 4);
            As[kq * 4 + 0][m] = aReg[q].x;
            As[kq * 4 + 1][m] = aReg[q].y;
            As[kq * 4 + 2][m] = aReg[q].z;
            As[kq * 4 + 3][m] = aReg[q].w;
        }
#pragma unroll
        for (int q = 0; q < BPT; q++) {
            int idx = tid + q * NT;
            int kk = idx / (BN / 2);
            int c2 = idx % (BN / 2);
            *(float2*)&Bs[kk][c2 * 2] = bReg[q];
        }
    };

    float2 acc[TM][TN / 2];
#pragma unroll
    for (int i = 0; i < TM; i++)
#pragma unroll
        for (int j = 0; j < TN / 2; j++) acc[i][j] = make_float2(0.f, 0.f);

    load_tiles(0);
    for (int k0 = 0; k0 < Kc; k0 += BK) {
        store_tiles();
        __syncthreads();
        if (k0 + BK < Kc) load_tiles(k0 + BK);

#pragma unroll
        for (int kk = 0; kk < BK; kk++) {
            float av[TM];
            float2 bv[TN / 2];
            if constexpr (TM % 4 == 0) {
#pragma unroll
                for (int i = 0; i < TM; i += 4) {
                    float4 v = *(const float4*)&As[kk][tr + i];
                    av[i] = v.x; av[i + 1] = v.y; av[i + 2] = v.z; av[i + 3] = v.w;
                }
            } else if constexpr (TM % 2 == 0) {
#pragma unroll
                for (int i = 0; i < TM; i += 2) {
                    float2 v = *(const float2*)&As[kk][tr + i];
                    av[i] = v.x; av[i + 1] = v.y;
                }
            } else {
#pragma unroll
                for (int i = 0; i < TM; i++) av[i] = As[kk][tr + i];
            }
            if constexpr (TN % 4 == 0) {
#pragma unroll
                for (int j = 0; j < TN / 4; j++) {
                    float4 v = *(const float4*)&Bs[kk][tc + j * 4];
                    bv[j * 2 + 0] = make_float2(v.x, v.y);
                    bv[j * 2 + 1] = make_float2(v.z, v.w);
                }
            } else {
#pragma unroll
                for (int j = 0; j < TN / 2; j++)
                    bv[j] = *(const float2*)&Bs[kk][tc + j * 2];
            }
#pragma unroll
            for (int i = 0; i < TM; i++) {
                float2 a2 = make_float2(av[i], av[i]);
#pragma unroll
                for (int j = 0; j < TN / 2; j++)
                    acc[i][j] = ffma2(a2, bv[j], acc[i][j]);
            }
        }
        __syncthreads();
    }

    if constexpr (SPLITS == 1) {
#pragma unroll
        for (int i = 0; i < TM; i++) {
            int gm = bm + tr + i;
#pragma unroll
            for (int j = 0; j < TN / 2; j++) {
#pragma unroll
                for (int h = 0; h < 2; h++) {
                    int gn = bn + tc + j * 2 + h;
                    if (gn < N) {
                        float v = ((h == 0) ? acc[i][j].x : acc[i][j].y) + bias[gn];
                        if (ACT) v = (v > 0.0f) ? v : 0.01f * v;
                        C[(size_t)gm * N + gn] = v;
                    }
                }
            }
        }
    } else {
        float* __restrict__ P = C + (size_t)blockIdx.z * M * N;
#pragma unroll
        for (int i = 0; i < TM; i++) {
            int gm = bm + tr + i;
#pragma unroll
            for (int j = 0; j < TN / 2; j++) {
                int gn = bn + tc + j * 2;
                if (gn + 2 <= N) {
                    *(float2*)&P[(size_t)gm * N + gn] = acc[i][j];
                } else if (gn < N) {
                    P[(size_t)gm * N + gn] = acc[i][j].x;
                }
            }
        }
    }
}

// ----------------------------------------------------------------------------
// h0: h0[128,512] = leaky(z[128,16] @ hW0[16,512] + hb0)
// ----------------------------------------------------------------------------
__global__ __launch_bounds__(256)
void h0_kernel(const float* __restrict__ z,
               const float* __restrict__ hW0,
               const float* __restrict__ hb0,
               float* __restrict__ h0)
{
    const int t = threadIdx.x;
    const int n0 = blockIdx.x * 4 + (t >> 7) * 2;
    const int m = t & 127;
    float2 acc = make_float2(0.f, 0.f);
#pragma unroll
    for (int k = 0; k < 16; k++) {
        float a = __ldg(&z[m * 16 + k]);
        float2 w = __ldg((const float2*)&hW0[k * 512 + n0]);
        acc = ffma2(make_float2(a, a), w, acc);
    }
    float2 bb = __ldg((const float2*)&hb0[n0]);
    float vx = acc.x + bb.x; vx = (vx > 0.f) ? vx : 0.01f * vx;
    float vy = acc.y + bb.y; vy = (vy > 0.f) ? vy : 0.01f * vy;
    *(float2*)&h0[m * 512 + n0] = make_float2(vx, vy);
}

// ----------------------------------------------------------------------------
// Split-K reduce + bias + leaky (h1/h2)
// ----------------------------------------------------------------------------
template<int ACT, int SPLITS>
__global__ void reduce_bias(const float* __restrict__ P,
                            const float* __restrict__ bias,
                            float* __restrict__ C, int M, int N)
{
    int i = blockIdx.x * blockDim.x + threadIdx.x;
    int MN = M * N;
    if (i >= MN) return;
    float s = 0.0f;
#pragma unroll
    for (int z = 0; z < SPLITS; z++) s += P[(size_t)z * MN + i];
    s += bias[i % N];
    if (ACT) s = (s > 0.0f) ? s : 0.01f * s;
    C[i] = s;
}

// ----------------------------------------------------------------------------
// Decoder with fused wab split-K(x2) reduce. One block per b,
// 512 threads = 4 j-groups x 128 g-lanes. MUFU sines.
// ----------------------------------------------------------------------------
#define DEC_NT 512
#define DEC_SMEM_FLOATS (8452 + 8452 + 64 * 128)

__global__ __launch_bounds__(DEC_NT)
void decoder_kernel(const float* __restrict__ logP,
                    const float* __restrict__ part,
                    const float* __restrict__ hbo,
                    float* __restrict__ out)
{
    extern __shared__ float s[];
    float* s_row = s;
    float* s_wgt = s + 8452;
    float* s_x   = s + 8452 + 8452;

    float* s_w0 = s_wgt;
    float* s_W1 = s_wgt + 64;
    float* s_W2 = s_wgt + 4160;
    float* s_w3 = s_wgt + 8256;
    float* s_b1 = s_wgt + 8320;
    float* s_b2 = s_wgt + 8384;
    float* s_sc = s_wgt + 8448;

    const int b = blockIdx.x;
    const int tid = threadIdx.x;

    // stage: wab_row[i] = part[0][b][i] + part[1][b][i] + hbo[i]
    {
        const float2* bias2 = (const float2*)hbo;
        const float2* p0 = (const float2*)(part + (size_t)b * OUTS);
        const size_t zs = (size_t)BSZ * OUTS / 2;
        float2* row2 = (float2*)s_row;
        for (int i = tid; i < OUTS / 2; i += DEC_NT) {
            float2 a = bias2[i];
            float2 v0 = p0[i];
            float2 v1 = p0[i + zs];
            a.x += v0.x + v1.x;
            a.y += v0.y + v1.y;
            row2[i] = a;
        }
    }
    __syncthreads();

    if (tid < 64) {
        s_w0[tid] = s_row[tid];
        s_b1[tid] = s_row[4161 + tid];
        s_b2[tid] = s_row[8321 + tid];
        s_w3[tid] = s_row[8385 + tid];
    }
    for (int i = tid; i < 4096; i += DEC_NT) {
        s_W1[i] = s_row[65 + i];
        s_W2[i] = s_row[4225 + i];
    }
    if (tid == 0) { s_sc[0] = s_row[64]; s_sc[1] = s_row[8449]; }
    __syncthreads();

    const int lane = tid & 127;
    const int grp = tid >> 7;          // 0..3
    const int j0 = grp * 16;
    const bool active = (lane < GSZ);
    float x_in = 0.0f;
    if (active) x_in = logP[b * GSZ + lane] * (1.0f / 3.0f);
    const float b0 = s_sc[0];
    const float b3 = s_sc[1];

    if (active) {
#pragma unroll
        for (int jj = 0; jj < 16; jj++) {
            float v = 30.0f * fmaf(x_in, s_w0[j0 + jj], b0);
            s_x[(j0 + jj) * 128 + lane] = fast_sin(v);
        }
    }
    __syncthreads();

    float2 acc[8];

    // layer 1
    if (active) {
#pragma unroll
        for (int q = 0; q < 8; q++) acc[q] = *(float2*)&s_b1[j0 + q * 2];
#pragma unroll 8
        for (int i = 0; i < 64; i++) {
            float a = s_x[i * 128 + lane];
            float2 a2 = make_float2(a, a);
#pragma unroll
            for (int q = 0; q < 4; q++) {
                float4 w = *(float4*)&s_W1[i * 64 + j0 + q * 4];
                acc[q * 2 + 0] = ffma2(a2, make_float2(w.x, w.y), acc[q * 2 + 0]);
                acc[q * 2 + 1] = ffma2(a2, make_float2(w.z, w.w), acc[q * 2 + 1]);
            }
        }
    }
    __syncthreads();
    if (active) {
#pragma unroll
        for (int q = 0; q < 8; q++) {
            s_x[(j0 + q * 2 + 0) * 128 + lane] = fast_sin(acc[q].x);
            s_x[(j0 + q * 2 + 1) * 128 + lane] = fast_sin(acc[q].y);
        }
    }
    __syncthreads();

    // layer 2
    if (active) {
#pragma unroll
        for (int q = 0; q < 8; q++) acc[q] = *(float2*)&s_b2[j0 + q * 2];
#pragma unroll 8
        for (int i = 0; i < 64; i++) {
            float a = s_x[i * 128 + lane];
            float2 a2 = make_float2(a, a);
#pragma unroll
            for (int q = 0; q < 4; q++) {
                float4 w = *(float4*)&s_W2[i * 64 + j0 + q * 4];
                acc[q * 2 + 0] = ffma2(a2, make_float2(w.x, w.y), acc[q * 2 + 0]);
                acc[q * 2 + 1] = ffma2(a2, make_float2(w.z, w.w), acc[q * 2 + 1]);
            }
        }
    }
    __syncthreads();
    if (active) {
#pragma unroll
        for (int q = 0; q < 8; q++) {
            s_x[(j0 + q * 2 + 0) * 128 + lane] = fast_sin(acc[q].x);
            s_x[(j0 + q * 2 + 1) * 128 + lane] = fast_sin(acc[q].y);
        }
    }
    __syncthreads();

    // layer 3 (scalar out): group 0 reduces
    if (grp == 0 && active) {
        float o = b3;
#pragma unroll 8
        for (int i = 0; i < 64; i++)
            o = fmaf(s_x[i * 128 + lane], s_w3[i], o);
        out[b * GSZ + lane] = fmaf(o, 500.0f, 1500.0f);
    }
}

// ----------------------------------------------------------------------------
extern "C" void kernel_launch(void* const* d_in, const int* in_sizes, int n_in,
                              void* d_out, int out_size)
{
    const float* z    = (const float*)d_in[0];
    const float* logP = (const float*)d_in[1];
    const float* hW0  = (const float*)d_in[2];
    const float* hb0  = (const float*)d_in[3];
    const float* hW1  = (const float*)d_in[4];
    const float* hb1  = (const float*)d_in[5];
    const float* hW2  = (const float*)d_in[6];
    const float* hb2  = (const float*)d_in[7];
    const float* hWo  = (const float*)d_in[8];
    const float* hbo  = (const float*)d_in[9];
    float* out = (float*)d_out;

    float *h0p, *h1p, *h2p, *partp;
    cudaGetSymbolAddress((void**)&h0p, g_h0);
    cudaGetSymbolAddress((void**)&h1p, g_h1);
    cudaGetSymbolAddress((void**)&h2p, g_h2);
    cudaGetSymbolAddress((void**)&partp, g_part);

    // h0: 128x512x16
    h0_kernel<<<128, 256>>>(z, hW0, hb0, h0p);

    // h1: 128x512x512, split-K x8, double-buffered
    gemm_db<32, 64, 32, 2, 4, 0, 8><<<dim3(HLDIM / 64, BSZ / 32, 8), 256>>>(
        h0p, hW1, hb1, partp, BSZ, HLDIM, HLDIM);
    reduce_bias<1, 8><<<(BSZ * HLDIM + 255) / 256, 256>>>(
        partp, hb1, h1p, BSZ, HLDIM);

    // h2
    gemm_db<32, 64, 32, 2, 4, 0, 8><<<dim3(HLDIM / 64, BSZ / 32, 8), 256>>>(
        h1p, hW2, hb2, partp, BSZ, HLDIM, HLDIM);
    reduce_bias<1, 8><<<(BSZ * HLDIM + 255) / 256, 256>>>(
        partp, hb2, h2p, BSZ, HLDIM);

    // wab: 128x8450x512, split-K x2 -> 134 CTAs, 16 pipelined k-iters
    gemm_db<128, 128, 16, 8, 8, 0, 2><<<dim3((OUTS + 127) / 128, 1, 2), 256>>>(
        h2p, hWo, hbo, partp, BSZ, OUTS, HLDIM);

    // decoder (fused wab reduce, MUFU sines)
    const int smem_bytes = DEC_SMEM_FLOATS * (int)sizeof(float);
    static int configured = 0;
    if (!configured) {
        cudaFuncSetAttribute(decoder_kernel,
                             cudaFuncAttributeMaxDynamicSharedMemorySize, smem_bytes);
        configured = 1;
    }
    decoder_kernel<<<BSZ, DEC_NT, smem_bytes>>>(logP, partp, hbo, out);
}